// round 3
// baseline (speedup 1.0000x reference)
#include <cuda_runtime.h>
#include <cuda_bf16.h>
#include <cstdint>

// MaxUnpooling2D scatter-add, software-pipelined per batch:
//   K0:  zero(b0)
//   Kk:  scatter(b_{k-1})  [blocks 0..4095]  ||  zero(b_k)  [blocks 4096..20479]
//   K8:  scatter(b7)
// Zeroing is DRAM-write-bound; scattering is L2-atomic/LSU-bound -> they
// overlap inside one kernel launch on disjoint SM resources, while each
// batch's 64MB output slice stays L2-resident between its zero and scatter.

static constexpr int B         = 8;
static constexpr int IN_PER_B  = 1 << 22;   // 4,194,304 elems (16 MB f32)
static constexpr int OUT_PER_B = 1 << 24;   // 16,777,216 elems (64 MB f32)

static constexpr int SCATTER_BLOCKS = (IN_PER_B / 4) / 256;   // 4096
static constexpr int ZERO_BLOCKS    = (OUT_PER_B / 4) / 256;  // 16384

__global__ void __launch_bounds__(256)
zero_batch_kernel(float4* __restrict__ out4)
{
    int i = blockIdx.x * blockDim.x + threadIdx.x;
    out4[i] = make_float4(0.f, 0.f, 0.f, 0.f);
}

// Combined: scatter batch `out_scatter` (zeroed by the previous launch) while
// zeroing batch `out_zero` for the next launch. out_zero==nullptr for the tail.
__global__ void __launch_bounds__(256)
pipe_kernel(const float4* __restrict__ vals4,
            const int4*  __restrict__ idx4,
            float* __restrict__ out_scatter,
            float4* __restrict__ out_zero)
{
    int bid = blockIdx.x;
    if (bid < SCATTER_BLOCKS) {
        int i = bid * 256 + threadIdx.x;
        float4 v = __ldcs(vals4 + i);
        int4   x = __ldcs(idx4 + i);
        atomicAdd(out_scatter + x.x, v.x);
        atomicAdd(out_scatter + x.y, v.y);
        atomicAdd(out_scatter + x.z, v.z);
        atomicAdd(out_scatter + x.w, v.w);
    } else {
        int i = (bid - SCATTER_BLOCKS) * 256 + threadIdx.x;
        out_zero[i] = make_float4(0.f, 0.f, 0.f, 0.f);
    }
}

extern "C" void kernel_launch(void* const* d_in, const int* in_sizes, int n_in,
                              void* d_out, int out_size)
{
    const float* vals = (const float*)d_in[0];
    const int*   idx  = (const int*)d_in[1];
    float* out = (float*)d_out;

    // Prologue: zero batch 0.
    zero_batch_kernel<<<ZERO_BLOCKS, 256>>>((float4*)out);

    // Pipeline: scatter(b) || zero(b+1).
    for (int b = 0; b < B - 1; b++) {
        pipe_kernel<<<SCATTER_BLOCKS + ZERO_BLOCKS, 256>>>(
            (const float4*)(vals + (size_t)b * IN_PER_B),
            (const int4*)(idx + (size_t)b * IN_PER_B),
            out + (size_t)b * OUT_PER_B,
            (float4*)(out + (size_t)(b + 1) * OUT_PER_B));
    }

    // Epilogue: scatter batch 7 only (no zero half).
    pipe_kernel<<<SCATTER_BLOCKS, 256>>>(
        (const float4*)(vals + (size_t)(B - 1) * IN_PER_B),
        (const int4*)(idx + (size_t)(B - 1) * IN_PER_B),
        out + (size_t)(B - 1) * OUT_PER_B,
        nullptr);
}